// round 11
// baseline (speedup 1.0000x reference)
#include <cuda_runtime.h>
#include <stdint.h>

// ============================================================================
// HopfieldNet — bit-exact reference model (locked Round 7):
//   PRNG:    JAX partitionable threefry: bits[t] = o0 ^ o1 of tf2x32(key,(0,t))
//   GEMM:    exact fp32, per-element single ascending-k FMA chain (FFMA2 packed,
//            per-lane rn — bit-identical to scalar)
//   sigmoid: p = 1/(1+exp(-z)), z = (2*h)*(1/T), libdevice expf, div.rn
// Round 11: split-N B fragment (lanes contiguous, 16B stride) -> B LDS at
// minimum wavefront cost (4/LDS.128 instead of 8); coalesced output stores.
// Single-buffer structure (R8) — double buffering measured as a regression.
// ============================================================================

#define NB   65536
#define ND   1024
#define NTOT (NB * ND)

#define BM 128
#define BN 128
#define BKT 16
#define TM 8
#define TN 8
#define APAD 4

__device__ float g_W [ND * ND];
__device__ float g_xA[NTOT];
__device__ float g_xB[NTOT];

// ---------------------------------------------------------------- threefry
__device__ __forceinline__ void tf2x32(uint32_t k0, uint32_t k1,
                                       uint32_t c0, uint32_t c1,
                                       uint32_t &o0, uint32_t &o1) {
    uint32_t ks2 = k0 ^ k1 ^ 0x1BD11BDAu;
    uint32_t x0 = c0 + k0;
    uint32_t x1 = c1 + k1;
#define TF_R(r) { x0 += x1; x1 = __funnelshift_l(x1, x1, (r)); x1 ^= x0; }
    TF_R(13) TF_R(15) TF_R(26) TF_R(6)   x0 += k1;  x1 += ks2 + 1u;
    TF_R(17) TF_R(29) TF_R(16) TF_R(24)  x0 += ks2; x1 += k0  + 2u;
    TF_R(13) TF_R(15) TF_R(26) TF_R(6)   x0 += k0;  x1 += k1  + 3u;
    TF_R(17) TF_R(29) TF_R(16) TF_R(24)  x0 += k1;  x1 += ks2 + 4u;
    TF_R(13) TF_R(15) TF_R(26) TF_R(6)   x0 += ks2; x1 += k0  + 5u;
#undef TF_R
    o0 = x0; o1 = x1;
}

__device__ __forceinline__ float jax_uniform(uint32_t k0, uint32_t k1, uint32_t t) {
    uint32_t o0, o1;
    tf2x32(k0, k1, 0u, t, o0, o1);
    uint32_t bits = o0 ^ o1;
    return __uint_as_float((bits >> 9) | 0x3f800000u) - 1.0f;
}

__device__ __forceinline__ float act(float h, float rT,
                                     uint32_t k0, uint32_t k1, uint32_t t) {
    float u = jax_uniform(k0, k1, t);
    float z = __fmul_rn(__fmul_rn(2.0f, h), rT);
    float e = expf(-z);
    float p = __fdiv_rn(1.0f, __fadd_rn(1.0f, e));
    return (u < p) ? 1.0f : -1.0f;
}

// ---------------------------------------------------------------- f32x2 ops
__device__ __forceinline__ uint64_t dup_f32x2(float a) {
    uint64_t r;
    asm("mov.b64 %0, {%1, %1};" : "=l"(r) : "f"(a));
    return r;
}
__device__ __forceinline__ void ffma2(uint64_t &acc, uint64_t a2, uint64_t b2) {
    asm("fma.rn.f32x2 %0, %1, %2, %0;" : "+l"(acc) : "l"(a2), "l"(b2));
}
__device__ __forceinline__ void unpack_f32x2(uint64_t v, float &lo, float &hi) {
    asm("mov.b64 {%0, %1}, %2;" : "=f"(lo), "=f"(hi) : "l"(v));
}

// ---------------------------------------------------------------- W = Wu+Wu^T
__global__ void prep_W(const float* __restrict__ Wu) {
    int idx = blockIdx.x * blockDim.x + threadIdx.x;
    int k = idx >> 10;
    int j = idx & 1023;
    g_W[idx] = __fadd_rn(Wu[idx], Wu[j * ND + k]);
}

// ---------------------------------------------------------------- fused step
// 256 threads, 8x8 outputs/thread, FFMA2 inner product.
// B fragment is SPLIT-N: cols {4tx..4tx+3} and {64+4tx..+3} -> lanes read
// contiguous 16B chunks (minimum smem wavefronts) and stores coalesce.
__global__ void __launch_bounds__(256)
hop_step(const float* __restrict__ X, float* __restrict__ O,
         uint32_t k0, uint32_t k1, float rT) {
    __shared__ float As[BKT][BM + APAD];
    __shared__ float Bs[BKT][BN];

    const int tid = threadIdx.x;
    const int tx  = tid & 15;
    const int ty  = tid >> 4;

    const int row0 = blockIdx.y * BM;
    const int col0 = blockIdx.x * BN;

    uint64_t acc[TM][TN / 2];
#pragma unroll
    for (int m = 0; m < TM; m++)
#pragma unroll
        for (int n = 0; n < TN / 2; n++) acc[m][n] = 0ull;

    for (int kt = 0; kt < ND; kt += BKT) {
#pragma unroll
        for (int l = 0; l < 2; l++) {
            int e = tid * 2 + l;
            int r = e >> 2;
            int c = (e & 3) * 4;
            float4 v = *(const float4*)&X[(size_t)(row0 + r) * ND + kt + c];
            As[c + 0][r] = v.x; As[c + 1][r] = v.y;
            As[c + 2][r] = v.z; As[c + 3][r] = v.w;
        }
#pragma unroll
        for (int l = 0; l < 2; l++) {
            int e  = tid * 2 + l;
            int kr = e >> 5;
            int c  = (e & 31) * 4;
            *(float4*)&Bs[kr][c] =
                *(const float4*)&g_W[(size_t)(kt + kr) * ND + col0 + c];
        }
        __syncthreads();

#pragma unroll
        for (int kk = 0; kk < BKT; kk++) {     // strict ascending k
            // a: 8 consecutive m (broadcast across 16 lanes) -> dup both lanes
            float4 av0 = *(const float4*)&As[kk][ty * TM];
            float4 av1 = *(const float4*)&As[kk][ty * TM + 4];
            uint64_t a2[TM];
            a2[0] = dup_f32x2(av0.x); a2[1] = dup_f32x2(av0.y);
            a2[2] = dup_f32x2(av0.z); a2[3] = dup_f32x2(av0.w);
            a2[4] = dup_f32x2(av1.x); a2[5] = dup_f32x2(av1.y);
            a2[6] = dup_f32x2(av1.z); a2[7] = dup_f32x2(av1.w);
            // b: SPLIT-N — two contiguous float4 groups, lanes stride 16B
            float4 bv0 = *(const float4*)&Bs[kk][tx * 4];         // cols 4tx..+3
            float4 bv1 = *(const float4*)&Bs[kk][64 + tx * 4];    // cols 64+4tx..+3
            uint64_t b2[TN / 2];
            b2[0] = ((const uint64_t*)&bv0)[0];
            b2[1] = ((const uint64_t*)&bv0)[1];
            b2[2] = ((const uint64_t*)&bv1)[0];
            b2[3] = ((const uint64_t*)&bv1)[1];
#pragma unroll
            for (int m = 0; m < TM; m++)
#pragma unroll
                for (int n = 0; n < TN / 2; n++)
                    ffma2(acc[m][n], a2[m], b2[n]);
        }
        __syncthreads();
    }

    // epilogue: two col groups per row: [col0+4tx .. +3], [col0+64+4tx .. +3]
#pragma unroll
    for (int m = 0; m < TM; m++) {
        const int gi  = row0 + ty * TM + m;
        const int gja = col0 + tx * 4;          // group 0 base
        const int gjb = col0 + 64 + tx * 4;     // group 1 base
        float o0f, o1f, o2f, o3f;
        {
            float lo, hi;
            uint32_t ta = ((uint32_t)gi << 10) | (uint32_t)gja;
            unpack_f32x2(acc[m][0], lo, hi);
            o0f = act(lo, rT, k0, k1, ta);
            o1f = act(hi, rT, k0, k1, ta + 1);
            unpack_f32x2(acc[m][1], lo, hi);
            o2f = act(lo, rT, k0, k1, ta + 2);
            o3f = act(hi, rT, k0, k1, ta + 3);
            *(float4*)&O[(size_t)gi * ND + gja] = make_float4(o0f, o1f, o2f, o3f);
        }
        {
            float lo, hi;
            uint32_t tb = ((uint32_t)gi << 10) | (uint32_t)gjb;
            unpack_f32x2(acc[m][2], lo, hi);
            o0f = act(lo, rT, k0, k1, tb);
            o1f = act(hi, rT, k0, k1, tb + 1);
            unpack_f32x2(acc[m][3], lo, hi);
            o2f = act(lo, rT, k0, k1, tb + 2);
            o3f = act(hi, rT, k0, k1, tb + 3);
            *(float4*)&O[(size_t)gi * ND + gjb] = make_float4(o0f, o1f, o2f, o3f);
        }
    }
}

// ---------------------------------------------------------------- host side
static inline uint32_t h_rotl(uint32_t x, int r) { return (x << r) | (x >> (32 - r)); }
static void h_tf2x32(uint32_t k0, uint32_t k1, uint32_t c0, uint32_t c1,
                     uint32_t* o0, uint32_t* o1) {
    uint32_t ks2 = k0 ^ k1 ^ 0x1BD11BDAu;
    uint32_t x0 = c0 + k0, x1 = c1 + k1;
#define HTF_R(r) { x0 += x1; x1 = h_rotl(x1, (r)); x1 ^= x0; }
    HTF_R(13) HTF_R(15) HTF_R(26) HTF_R(6)   x0 += k1;  x1 += ks2 + 1u;
    HTF_R(17) HTF_R(29) HTF_R(16) HTF_R(24)  x0 += ks2; x1 += k0  + 2u;
    HTF_R(13) HTF_R(15) HTF_R(26) HTF_R(6)   x0 += k0;  x1 += k1  + 3u;
    HTF_R(17) HTF_R(29) HTF_R(16) HTF_R(24)  x0 += k1;  x1 += ks2 + 4u;
    HTF_R(13) HTF_R(15) HTF_R(26) HTF_R(6)   x0 += ks2; x1 += k0  + 5u;
#undef HTF_R
    *o0 = x0; *o1 = x1;
}

extern "C" void kernel_launch(void* const* d_in, const int* in_sizes, int n_in,
                              void* d_out, int out_size) {
    const float* x0 = (const float*)d_in[0];   // (65536, 1024) f32
    const float* Wu = (const float*)d_in[1];   // (1024, 1024)  f32

    float *xA, *xB;
    cudaGetSymbolAddress((void**)&xA, g_xA);
    cudaGetSymbolAddress((void**)&xB, g_xB);

    prep_W<<<(ND * ND) / 256, 256>>>(Wu);

    uint32_t keys[10][2];
    for (int i = 0; i < 10; i++)
        h_tf2x32(0u, 42u, 0u, (uint32_t)i, &keys[i][0], &keys[i][1]);

    dim3 grid(ND / BN, NB / BM);   // (8, 512)
    const float* src = x0;
    for (int i = 0; i < 10; i++) {
        volatile float T  = (float)(1.0 / (double)(2 * i + 1));
        volatile float rT = 1.0f / T;
        float* dst = (i == 9) ? (float*)d_out : (((i & 1) == 0) ? xA : xB);
        hop_step<<<grid, 256>>>(src, dst, keys[i][0], keys[i][1], rT);
        src = dst;
    }
}

// round 12
// speedup vs baseline: 1.5789x; 1.5789x over previous
#include <cuda_runtime.h>
#include <stdint.h>

// ============================================================================
// HopfieldNet — bit-exact reference model (locked Round 7):
//   PRNG:    JAX partitionable threefry: bits[t] = o0 ^ o1 of tf2x32(key,(0,t))
//   GEMM:    exact fp32, per-element single ascending-k FMA chain (FFMA2 packed,
//            per-lane rn — bit-identical to scalar)
//   sigmoid: p = 1/(1+exp(-z)), z = (2*h)*(1/T), libdevice expf, div.rn
// Round 12: R8 kernel + cp.async double-buffered B tile (zero staging regs),
// register-staged A (8 regs), one barrier per tile. Inner loop & epilogue
// byte-identical to R8 (fastest passing version).
// ============================================================================

#define NB   65536
#define ND   1024
#define NTOT (NB * ND)

#define BM 128
#define BN 128
#define BKT 16
#define NKT (ND / BKT)
#define TM 8
#define TN 8
#define APAD 4

__device__ float g_W [ND * ND];
__device__ float g_xA[NTOT];
__device__ float g_xB[NTOT];

// ---------------------------------------------------------------- threefry
__device__ __forceinline__ void tf2x32(uint32_t k0, uint32_t k1,
                                       uint32_t c0, uint32_t c1,
                                       uint32_t &o0, uint32_t &o1) {
    uint32_t ks2 = k0 ^ k1 ^ 0x1BD11BDAu;
    uint32_t x0 = c0 + k0;
    uint32_t x1 = c1 + k1;
#define TF_R(r) { x0 += x1; x1 = __funnelshift_l(x1, x1, (r)); x1 ^= x0; }
    TF_R(13) TF_R(15) TF_R(26) TF_R(6)   x0 += k1;  x1 += ks2 + 1u;
    TF_R(17) TF_R(29) TF_R(16) TF_R(24)  x0 += ks2; x1 += k0  + 2u;
    TF_R(13) TF_R(15) TF_R(26) TF_R(6)   x0 += k0;  x1 += k1  + 3u;
    TF_R(17) TF_R(29) TF_R(16) TF_R(24)  x0 += k1;  x1 += ks2 + 4u;
    TF_R(13) TF_R(15) TF_R(26) TF_R(6)   x0 += ks2; x1 += k0  + 5u;
#undef TF_R
    o0 = x0; o1 = x1;
}

__device__ __forceinline__ float jax_uniform(uint32_t k0, uint32_t k1, uint32_t t) {
    uint32_t o0, o1;
    tf2x32(k0, k1, 0u, t, o0, o1);
    uint32_t bits = o0 ^ o1;
    return __uint_as_float((bits >> 9) | 0x3f800000u) - 1.0f;
}

__device__ __forceinline__ float act(float h, float rT,
                                     uint32_t k0, uint32_t k1, uint32_t t) {
    float u = jax_uniform(k0, k1, t);
    float z = __fmul_rn(__fmul_rn(2.0f, h), rT);
    float e = expf(-z);
    float p = __fdiv_rn(1.0f, __fadd_rn(1.0f, e));
    return (u < p) ? 1.0f : -1.0f;
}

// ---------------------------------------------------------------- f32x2 ops
__device__ __forceinline__ uint64_t dup_f32x2(float a) {
    uint64_t r;
    asm("mov.b64 %0, {%1, %1};" : "=l"(r) : "f"(a));
    return r;
}
__device__ __forceinline__ void ffma2(uint64_t &acc, uint64_t a2, uint64_t b2) {
    asm("fma.rn.f32x2 %0, %1, %2, %0;" : "+l"(acc) : "l"(a2), "l"(b2));
}
__device__ __forceinline__ void unpack_f32x2(uint64_t v, float &lo, float &hi) {
    asm("mov.b64 {%0, %1}, %2;" : "=f"(lo), "=f"(hi) : "l"(v));
}

// ---------------------------------------------------------------- cp.async
__device__ __forceinline__ uint32_t smem_u32(const void* p) {
    return (uint32_t)__cvta_generic_to_shared(p);
}
__device__ __forceinline__ void cp_async16(uint32_t dst, const void* src) {
    asm volatile("cp.async.cg.shared.global [%0], [%1], 16;"
                 :: "r"(dst), "l"(src));
}
__device__ __forceinline__ void cp_async_commit() {
    asm volatile("cp.async.commit_group;");
}
__device__ __forceinline__ void cp_async_wait0() {
    asm volatile("cp.async.wait_group 0;");
}

// ---------------------------------------------------------------- W = Wu+Wu^T
__global__ void prep_W(const float* __restrict__ Wu) {
    int idx = blockIdx.x * blockDim.x + threadIdx.x;
    int k = idx >> 10;
    int j = idx & 1023;
    g_W[idx] = __fadd_rn(Wu[idx], Wu[j * ND + k]);
}

// ---------------------------------------------------------------- fused step
// 256 threads, 8x8 outputs/thread, FFMA2 inner product (R8 layout).
// Pipeline: B via cp.async double buffer, A via 8-reg staging, 1 sync/tile.
__global__ void __launch_bounds__(256)
hop_step(const float* __restrict__ X, float* __restrict__ O,
         uint32_t k0, uint32_t k1, float rT) {
    __shared__ float As[2][BKT][BM + APAD];
    __shared__ float Bs[2][BKT][BN];

    const int tid = threadIdx.x;
    const int tx  = tid & 15;
    const int ty  = tid >> 4;

    const int row0 = blockIdx.y * BM;
    const int col0 = blockIdx.x * BN;

    // per-thread load coords (2 float4 each for A and B)
    const int ar0 = (tid * 2)     >> 2;
    const int ac0 = ((tid * 2) & 3) * 4;
    const int ar1 = (tid * 2 + 1) >> 2;
    const int ac1 = ((tid * 2 + 1) & 3) * 4;
    const int bk0 = (tid * 2)     >> 5;
    const int bc0 = ((tid * 2) & 31) * 4;
    const int bk1 = (tid * 2 + 1) >> 5;
    const int bc1 = ((tid * 2 + 1) & 31) * 4;

    const uint32_t bs0 = smem_u32(&Bs[0][bk0][bc0]);
    const uint32_t bs1 = smem_u32(&Bs[0][bk1][bc1]);
    const uint32_t bufstride = (uint32_t)(BKT * BN * 4);
    const float* gb0 = &g_W[(size_t)bk0 * ND + col0 + bc0];
    const float* gb1 = &g_W[(size_t)bk1 * ND + col0 + bc1];
    const float* ga0 = &X[(size_t)(row0 + ar0) * ND + ac0];
    const float* ga1 = &X[(size_t)(row0 + ar1) * ND + ac1];

    uint64_t acc[TM][TN / 2];
#pragma unroll
    for (int m = 0; m < TM; m++)
#pragma unroll
        for (int n = 0; n < TN / 2; n++) acc[m][n] = 0ull;

    // ---- prologue: tile 0 -> buffer 0 (B async, A through regs)
    {
        cp_async16(bs0, gb0);
        cp_async16(bs1, gb1);
        cp_async_commit();
        float4 a0 = *(const float4*)ga0;
        float4 a1 = *(const float4*)ga1;
        As[0][ac0 + 0][ar0] = a0.x; As[0][ac0 + 1][ar0] = a0.y;
        As[0][ac0 + 2][ar0] = a0.z; As[0][ac0 + 3][ar0] = a0.w;
        As[0][ac1 + 0][ar1] = a1.x; As[0][ac1 + 1][ar1] = a1.y;
        As[0][ac1 + 2][ar1] = a1.z; As[0][ac1 + 3][ar1] = a1.w;
        cp_async_wait0();
    }
    __syncthreads();

    for (int t = 0; t < NKT; t++) {
        const int buf = t & 1;

        float4 na0, na1;
        if (t + 1 < NKT) {
            const int kt = (t + 1) * BKT;
            // next B tile: straight to the other smem buffer, zero regs
            cp_async16(bs0 + (uint32_t)(buf ^ 1) * bufstride,
                       gb0 + (size_t)kt * ND);
            cp_async16(bs1 + (uint32_t)(buf ^ 1) * bufstride,
                       gb1 + (size_t)kt * ND);
            cp_async_commit();
            // next A tile: stage in 8 regs (transpose on store later)
            na0 = *(const float4*)(ga0 + kt);
            na1 = *(const float4*)(ga1 + kt);
        }

        // ---- compute current tile (byte-identical to R8 inner loop)
#pragma unroll
        for (int kk = 0; kk < BKT; kk++) {
            float4 av0 = *(const float4*)&As[buf][kk][ty * TM];
            float4 av1 = *(const float4*)&As[buf][kk][ty * TM + 4];
            uint64_t a2[TM];
            a2[0] = dup_f32x2(av0.x); a2[1] = dup_f32x2(av0.y);
            a2[2] = dup_f32x2(av0.z); a2[3] = dup_f32x2(av0.w);
            a2[4] = dup_f32x2(av1.x); a2[5] = dup_f32x2(av1.y);
            a2[6] = dup_f32x2(av1.z); a2[7] = dup_f32x2(av1.w);
            float4 bv0 = *(const float4*)&Bs[buf][kk][tx * TN];
            float4 bv1 = *(const float4*)&Bs[buf][kk][tx * TN + 4];
            uint64_t b2[TN / 2];
            b2[0] = ((const uint64_t*)&bv0)[0];
            b2[1] = ((const uint64_t*)&bv0)[1];
            b2[2] = ((const uint64_t*)&bv1)[0];
            b2[3] = ((const uint64_t*)&bv1)[1];
#pragma unroll
            for (int m = 0; m < TM; m++)
#pragma unroll
                for (int n = 0; n < TN / 2; n++)
                    ffma2(acc[m][n], a2[m], b2[n]);
        }

        if (t + 1 < NKT) {
            const int nbuf = buf ^ 1;
            As[nbuf][ac0 + 0][ar0] = na0.x; As[nbuf][ac0 + 1][ar0] = na0.y;
            As[nbuf][ac0 + 2][ar0] = na0.z; As[nbuf][ac0 + 3][ar0] = na0.w;
            As[nbuf][ac1 + 0][ar1] = na1.x; As[nbuf][ac1 + 1][ar1] = na1.y;
            As[nbuf][ac1 + 2][ar1] = na1.z; As[nbuf][ac1 + 3][ar1] = na1.w;
            cp_async_wait0();
            __syncthreads();
        }
    }

    // ---- epilogue (byte-identical to R8)
#pragma unroll
    for (int m = 0; m < TM; m++) {
        const int gi = row0 + ty * TM + m;
        const int gj0 = col0 + tx * TN;
        float out[TN];
#pragma unroll
        for (int n = 0; n < TN / 2; n++) {
            float lo, hi;
            unpack_f32x2(acc[m][n], lo, hi);
            uint32_t tl = ((uint32_t)gi << 10) | (uint32_t)(gj0 + 2 * n);
            out[2 * n]     = act(lo, rT, k0, k1, tl);
            out[2 * n + 1] = act(hi, rT, k0, k1, tl + 1);
        }
        float4* dst = (float4*)&O[(size_t)gi * ND + gj0];
        dst[0] = make_float4(out[0], out[1], out[2], out[3]);
        dst[1] = make_float4(out[4], out[5], out[6], out[7]);
    }
}

// ---------------------------------------------------------------- host side
static inline uint32_t h_rotl(uint32_t x, int r) { return (x << r) | (x >> (32 - r)); }
static void h_tf2x32(uint32_t k0, uint32_t k1, uint32_t c0, uint32_t c1,
                     uint32_t* o0, uint32_t* o1) {
    uint32_t ks2 = k0 ^ k1 ^ 0x1BD11BDAu;
    uint32_t x0 = c0 + k0, x1 = c1 + k1;
#define HTF_R(r) { x0 += x1; x1 = h_rotl(x1, (r)); x1 ^= x0; }
    HTF_R(13) HTF_R(15) HTF_R(26) HTF_R(6)   x0 += k1;  x1 += ks2 + 1u;
    HTF_R(17) HTF_R(29) HTF_R(16) HTF_R(24)  x0 += ks2; x1 += k0  + 2u;
    HTF_R(13) HTF_R(15) HTF_R(26) HTF_R(6)   x0 += k0;  x1 += k1  + 3u;
    HTF_R(17) HTF_R(29) HTF_R(16) HTF_R(24)  x0 += k1;  x1 += ks2 + 4u;
    HTF_R(13) HTF_R(15) HTF_R(26) HTF_R(6)   x0 += ks2; x1 += k0  + 5u;
#undef HTF_R
    *o0 = x0; *o1 = x1;
}

extern "C" void kernel_launch(void* const* d_in, const int* in_sizes, int n_in,
                              void* d_out, int out_size) {
    const float* x0 = (const float*)d_in[0];   // (65536, 1024) f32
    const float* Wu = (const float*)d_in[1];   // (1024, 1024)  f32

    float *xA, *xB;
    cudaGetSymbolAddress((void**)&xA, g_xA);
    cudaGetSymbolAddress((void**)&xB, g_xB);

    prep_W<<<(ND * ND) / 256, 256>>>(Wu);

    uint32_t keys[10][2];
    for (int i = 0; i < 10; i++)
        h_tf2x32(0u, 42u, 0u, (uint32_t)i, &keys[i][0], &keys[i][1]);

    dim3 grid(ND / BN, NB / BM);   // (8, 512)
    const float* src = x0;
    for (int i = 0; i < 10; i++) {
        volatile float T  = (float)(1.0 / (double)(2 * i + 1));
        volatile float rT = 1.0f / T;
        float* dst = (i == 9) ? (float*)d_out : (((i & 1) == 0) ? xA : xB);
        hop_step<<<grid, 256>>>(src, dst, keys[i][0], keys[i][1], rT);
        src = dst;
    }
}